// round 16
// baseline (speedup 1.0000x reference)
#include <cuda_runtime.h>
#include <cuda_fp16.h>
#include <cstdint>
#include <math.h>

// ---------------------------------------------------------------------------
// 8-expert FFN, fp32: per expert [2048x2048]@[2048x8192] -> GELU -> @[8192x2048]
// compute_103 portable path. R16 = R15 (fp16 mma.m16n8k16, BK=64, 3 stages,
// 2 CTAs/SM, race-free cross-tile pipeline, HW tanh) made PERSISTENT:
// 2*numSMs CTAs grid-stride over output-tile jobs with ONE warm cp.async
// stage ring spanning job boundaries — prologue paid once per CTA, no wave
// transitions, epilogue overlapped with the next job's in-flight loads.
// ---------------------------------------------------------------------------
#define EXP_E 8
#define EXP_C 2048
#define EXP_D 2048
#define EXP_F 8192

__device__ __align__(256) __half g_H  [(size_t)EXP_E * EXP_C * EXP_F];  // gelu(X@W1+b1)
__device__ __align__(256) __half g_Xh [(size_t)EXP_E * EXP_C * EXP_D];  // half X
__device__ __align__(256) __half g_W1h[(size_t)EXP_E * EXP_D * EXP_F];  // [E][D/64][F][64]
__device__ __align__(256) __half g_W2h[(size_t)EXP_E * EXP_F * EXP_D];  // [E][F/64][D][64]

#define BM 128
#define BN 128
#define BK 64
#define STAGES 3
#define ROW_BYTES 128                       // 64 halves per k-row
#define A_BYTES (BM * ROW_BYTES)            // 16384
#define B_BYTES (BN * ROW_BYTES)            // 16384
#define STAGE_BYTES (A_BYTES + B_BYTES)     // 32768
#define SMEM_BYTES (STAGES * STAGE_BYTES)   // 98304/CTA; 2 CTAs = 192KB/SM

// ---------------------------------------------------------------------------
// Helpers
// ---------------------------------------------------------------------------
__device__ __forceinline__ uint32_t smem_u32(const void* p) {
    uint32_t a;
    asm("{ .reg .u64 t; cvta.to.shared.u64 t, %1; cvt.u32.u64 %0, t; }"
        : "=r"(a) : "l"(p));
    return a;
}

#define CP_ASYNC_CG(dst_u32, src_ptr) \
    asm volatile("cp.async.cg.shared.global [%0], [%1], 16;" \
                 :: "r"(dst_u32), "l"(src_ptr) : "memory")
#define CP_ASYNC_COMMIT() asm volatile("cp.async.commit_group;" ::: "memory")
#define CP_ASYNC_WAIT(n)  asm volatile("cp.async.wait_group %0;" :: "n"(n) : "memory")

#define LDSM_X4(r, addr) \
    asm volatile("ldmatrix.sync.aligned.m8n8.x4.shared.b16 {%0,%1,%2,%3}, [%4];" \
                 : "=r"((r)[0]), "=r"((r)[1]), "=r"((r)[2]), "=r"((r)[3]) \
                 : "r"(addr))

// fp16 MMA, fp32 accumulate
__device__ __forceinline__ void mma_f16(float* d, const uint32_t* a,
                                        uint32_t b0, uint32_t b1) {
    asm volatile(
        "mma.sync.aligned.m16n8k16.row.col.f32.f16.f16.f32 "
        "{%0,%1,%2,%3}, {%4,%5,%6,%7}, {%8,%9}, {%0,%1,%2,%3};"
        : "+f"(d[0]), "+f"(d[1]), "+f"(d[2]), "+f"(d[3])
        : "r"(a[0]), "r"(a[1]), "r"(a[2]), "r"(a[3]), "r"(b0), "r"(b1));
}

// HW tanh (sm_75+ MUFU): single instruction, max err ~2^-11.
__device__ __forceinline__ float tanh_hw(float x) {
    float y;
    asm("tanh.approx.f32 %0, %1;" : "=f"(y) : "f"(x));
    return y;
}

__device__ __forceinline__ float gelu_tanh(float x) {
    float u = 0.7978845608028654f * fmaf(0.044715f * x, x * x, x);
    return 0.5f * x * (1.0f + tanh_hw(u));
}

// Convert X: fp32 -> fp16 (RNE).
__global__ void __launch_bounds__(256)
to_half_pass(const float4* __restrict__ in, uint2* __restrict__ out, size_t n4) {
    size_t i = (size_t)blockIdx.x * blockDim.x + threadIdx.x;
    size_t stride = (size_t)gridDim.x * blockDim.x;
    for (; i < n4; i += stride) {
        float4 v = in[i];
        __half2 h0 = __floats2half2_rn(v.x, v.y);
        __half2 h1 = __floats2half2_rn(v.z, v.w);
        uint2 u;
        u.x = *reinterpret_cast<uint32_t*>(&h0);
        u.y = *reinterpret_cast<uint32_t*>(&h1);
        out[i] = u;
    }
}

// Transpose-pack weights to half, 64-wide: W[e][k][n] -> Wt[e][k/64][n][64].
__global__ void __launch_bounds__(256)
transpose_pack64_h(const float* __restrict__ W, __half* __restrict__ Wt,
                   int K, int N) {
    const int n  = blockIdx.x * 256 + threadIdx.x;
    const int kt = blockIdx.y;
    const int e  = blockIdx.z;
    const float* src = W + ((size_t)e * K + (size_t)kt * 64) * N + n;
    __half* dst = Wt + (((size_t)e * (K / 64) + kt) * N + n) * 64;
#pragma unroll
    for (int j = 0; j < 64; j += 8) {
        uint4 u;
        __half2 h;
        h = __floats2half2_rn(src[(size_t)(j+0)*N], src[(size_t)(j+1)*N]);
        u.x = *reinterpret_cast<uint32_t*>(&h);
        h = __floats2half2_rn(src[(size_t)(j+2)*N], src[(size_t)(j+3)*N]);
        u.y = *reinterpret_cast<uint32_t*>(&h);
        h = __floats2half2_rn(src[(size_t)(j+4)*N], src[(size_t)(j+5)*N]);
        u.z = *reinterpret_cast<uint32_t*>(&h);
        h = __floats2half2_rn(src[(size_t)(j+6)*N], src[(size_t)(j+7)*N]);
        u.w = *reinterpret_cast<uint32_t*>(&h);
        *reinterpret_cast<uint4*>(dst + j) = u;
    }
}

// ---------------------------------------------------------------------------
// Persistent batched GEMM:
//   Out[e][m][n] = epi( sum_k A[e][m][k]*B[e][k][n] + bias[e][n] )
//   A:  [E][2048][K] row-major half;  Bt: [E][K/64][ldN][64] packed half
//   Job = one 128x128 output tile. job -> (m = job&15, n = (job>>4)&(NB-1),
//   e = job>>(4+nbs)), m fastest so concurrent CTAs share B tiles in L2.
//   CTA: 128 threads (warp grid 2x2 of 64x64), 2 CTAs/SM, grid = 2*numSMs.
// ---------------------------------------------------------------------------
template <bool GELU, typename OutT>
__global__ void __launch_bounds__(128, 2)
moe_gemm_f16(const __half* __restrict__ A, const __half* __restrict__ Bt,
             const float* __restrict__ bias, OutT* __restrict__ Out,
             int K, int ldN, int njobs, int nbs)
{
    extern __shared__ char smem[];
    const int tid  = threadIdx.x;
    const int warp = tid >> 5;
    const int lane = tid & 31;
    const int KT = K / BK;
    const int stride = gridDim.x;

    const uint32_t sbase = smem_u32(smem);

    const int wm = warp >> 1;    // warp grid 2(M) x 2(N), warp tile 64x64
    const int wn = warp & 1;

    // ---- cp.async geometry ----
    const int crow   = tid >> 3;              // 0..15
    const int cchunk = tid & 7;               // 8 x 16B per 128B row
    const int cswz   = crow & 7;
    const uint32_t a_dst0 = (uint32_t)(crow * ROW_BYTES + ((cchunk ^ cswz) * 16));

    // ---- ldmatrix geometry (kk-step address = base ^ (kk*32)) ----
    const int alrow = (lane & 7) + ((lane >> 3) & 1) * 8;
    const int ahi   = lane >> 4;
    const int blrow = (lane & 7) + ((lane >> 4) & 1) * 8;
    const int bhi   = (lane >> 3) & 1;
    uint32_t afrag[4], bfrag[4];
#pragma unroll
    for (int i = 0; i < 4; ++i) {
        int ra = wm * 64 + i * 16 + alrow;
        afrag[i] = (uint32_t)(ra * ROW_BYTES + ((ahi ^ (ra & 7)) * 16));
        int rb = wn * 64 + i * 16 + blrow;
        bfrag[i] = (uint32_t)(A_BYTES + rb * ROW_BYTES + ((bhi ^ (rb & 7)) * 16));
    }

    float acc[4][8][4];
#pragma unroll
    for (int mt = 0; mt < 4; ++mt)
#pragma unroll
        for (int nt = 0; nt < 8; ++nt)
#pragma unroll
            for (int j = 0; j < 4; ++j) acc[mt][nt][j] = 0.0f;

    // ---- issue-side cursor (runs up to 3 tiles / 1 job ahead) ----
    int  ij = blockIdx.x;            // issue job
    int  it = 0;                     // tile within issue job
    bool issue_ok = (ij < njobs);
    const __half* a_run = A;
    const __half* b_run = Bt;
    auto set_issue_job = [&](int j) {
        int m0j = (j & 15) * BM;
        int r   = j >> 4;
        int n0j = (r & ((1 << nbs) - 1)) * BN;
        int ej  = r >> nbs;
        a_run = A  + (size_t)ej * EXP_C * K + (size_t)(m0j + crow) * K + cchunk * 8;
        b_run = Bt + (size_t)ej * (K / 64) * ldN * 64 + (size_t)n0j * 64
                   + (size_t)crow * 64 + cchunk * 8;
    };
    if (issue_ok) set_issue_job(ij);

    auto issue_one = [&](int stg) {
        if (issue_ok) {
            const uint32_t st = sbase + (uint32_t)stg * STAGE_BYTES;
#pragma unroll
            for (int rep = 0; rep < 8; ++rep)
                CP_ASYNC_CG(st + a_dst0 + rep * 16u * ROW_BYTES,
                            a_run + (size_t)rep * 16 * K);
#pragma unroll
            for (int rep = 0; rep < 8; ++rep)
                CP_ASYNC_CG(st + A_BYTES + a_dst0 + rep * 16u * ROW_BYTES,
                            b_run + rep * 16 * 64);
            a_run += BK;
            b_run += (size_t)ldN * 64;
            if (++it == KT) {
                it = 0;
                ij += stride;
                issue_ok = (ij < njobs);
                if (issue_ok) set_issue_job(ij);
            }
        }
    };

    // prologue (once per CTA): fill all 3 stages, preload first fragments
#pragma unroll
    for (int s = 0; s < STAGES; ++s) {
        issue_one(s);
        CP_ASYNC_COMMIT();
    }
    CP_ASYNC_WAIT(2);
    __syncthreads();

    uint32_t af[2][4][4], bf[2][4][4];
#pragma unroll
    for (int i = 0; i < 4; ++i) LDSM_X4(af[0][i], sbase + afrag[i]);
#pragma unroll
    for (int i = 0; i < 4; ++i) LDSM_X4(bf[0][i], sbase + bfrag[i]);

    const int g     = lane >> 2;
    const int cpair = (lane & 3) * 2;

    int s_cur = 0;
    for (int job = blockIdx.x; job < njobs; job += stride) {
        for (int t = 0; t < KT; ++t) {
            const uint32_t sA = sbase + (uint32_t)s_cur * STAGE_BYTES;
            const int s_nxt = (s_cur + 1 == STAGES) ? 0 : s_cur + 1;
            const uint32_t sN = sbase + (uint32_t)s_nxt * STAGE_BYTES;

#pragma unroll
            for (int kk = 0; kk < 4; ++kk) {
                const int cur = kk & 1, nxt = cur ^ 1;
                if (kk < 3) {
                    const uint32_t x = (uint32_t)(kk + 1) * 32u;
#pragma unroll
                    for (int i = 0; i < 4; ++i) LDSM_X4(af[nxt][i], sA + (afrag[i] ^ x));
#pragma unroll
                    for (int i = 0; i < 4; ++i) LDSM_X4(bf[nxt][i], sA + (bfrag[i] ^ x));
                } else {
                    // boundary: pending groups {next, next+1}; WAIT(1)
                    // guarantees the next consume tile's data has landed.
                    CP_ASYNC_WAIT(1);
                    __syncthreads();
                    if ((t + 1 < KT) || (job + stride < njobs)) {
#pragma unroll
                        for (int i = 0; i < 4; ++i) LDSM_X4(af[nxt][i], sN + afrag[i]);
#pragma unroll
                        for (int i = 0; i < 4; ++i) LDSM_X4(bf[nxt][i], sN + bfrag[i]);
                    }
                    issue_one(s_cur);      // refill freed stage (3 tiles ahead)
                    CP_ASYNC_COMMIT();     // uniform group count (empty ok)
                }
#pragma unroll
                for (int mt = 0; mt < 4; ++mt)
#pragma unroll
                    for (int nt = 0; nt < 8; ++nt)
                        mma_f16(acc[mt][nt], af[cur][mt],
                                bf[cur][nt >> 1][(nt & 1) * 2],
                                bf[cur][nt >> 1][(nt & 1) * 2 + 1]);
            }
            s_cur = s_nxt;
        }

        // ---- epilogue for this job (regs only; stage ring untouched) ----
        {
            const int m0 = (job & 15) * BM;
            const int r  = job >> 4;
            const int n0 = (r & ((1 << nbs) - 1)) * BN;
            const int e  = r >> nbs;
            const float* be = bias + (size_t)e * ldN;
            OutT*        Oe = Out  + (size_t)e * EXP_C * ldN;
#pragma unroll
            for (int mt = 0; mt < 4; ++mt) {
#pragma unroll
                for (int h = 0; h < 2; ++h) {
                    const int grow = m0 + wm * 64 + mt * 16 + g + h * 8;
                    OutT* op = Oe + (size_t)grow * ldN + n0 + wn * 64 + cpair;
#pragma unroll
                    for (int nt = 0; nt < 8; ++nt) {
                        const float2 bv = *reinterpret_cast<const float2*>(
                            be + n0 + wn * 64 + nt * 8 + cpair);
                        float x0 = acc[mt][nt][h * 2]     + bv.x;
                        float x1 = acc[mt][nt][h * 2 + 1] + bv.y;
                        if (GELU) {
                            __half2 hv = __floats2half2_rn(gelu_tanh(x0), gelu_tanh(x1));
                            *reinterpret_cast<__half2*>((__half*)op + nt * 8) = hv;
                        } else {
                            *reinterpret_cast<float2*>((float*)op + nt * 8) =
                                make_float2(x0, x1);
                        }
                        acc[mt][nt][h * 2]     = 0.0f;
                        acc[mt][nt][h * 2 + 1] = 0.0f;
                    }
                }
            }
        }
    }
}

// ---------------------------------------------------------------------------
// kernel_launch
// ---------------------------------------------------------------------------
extern "C" void kernel_launch(void* const* d_in, const int* in_sizes, int n_in,
                              void* d_out, int out_size) {
    (void)in_sizes; (void)n_in; (void)out_size;
    const float* inputs = (const float*)d_in[0];
    const float* w1     = (const float*)d_in[1];
    const float* b1     = (const float*)d_in[2];
    const float* w2     = (const float*)d_in[3];
    const float* b2     = (const float*)d_in[4];
    float* out = (float*)d_out;

    void *hp, *xp, *w1p, *w2p;
    cudaGetSymbolAddress(&hp,  g_H);
    cudaGetSymbolAddress(&xp,  g_Xh);
    cudaGetSymbolAddress(&w1p, g_W1h);
    cudaGetSymbolAddress(&w2p, g_W2h);
    __half* H   = (__half*)hp;
    __half* Xh  = (__half*)xp;
    __half* W1h = (__half*)w1p;
    __half* W2h = (__half*)w2p;

    const size_t nX = (size_t)EXP_E * EXP_C * EXP_D / 4;
    to_half_pass<<<2048, 256>>>((const float4*)inputs, (uint2*)Xh, nX);

    dim3 t1(EXP_F / 256, EXP_D / 64, EXP_E);   // W1: K=D, N=F
    transpose_pack64_h<<<t1, 256>>>(w1, W1h, EXP_D, EXP_F);
    dim3 t2(EXP_D / 256, EXP_F / 64, EXP_E);   // W2: K=F, N=D
    transpose_pack64_h<<<t2, 256>>>(w2, W2h, EXP_F, EXP_D);

    cudaFuncSetAttribute((const void*)moe_gemm_f16<true, __half>,
                         cudaFuncAttributeMaxDynamicSharedMemorySize, SMEM_BYTES);
    cudaFuncSetAttribute((const void*)moe_gemm_f16<false, float>,
                         cudaFuncAttributeMaxDynamicSharedMemorySize, SMEM_BYTES);

    int dev = 0, sms = 148;
    cudaGetDevice(&dev);
    cudaDeviceGetAttribute(&sms, cudaDevAttrMultiProcessorCount, dev);
    const int grid = sms * 2;                  // persistent: 2 CTAs per SM

    const int njobs1 = 16 * (EXP_F / BN) * EXP_E;   // 8192, nbs = 6
    const int njobs2 = 16 * (EXP_D / BN) * EXP_E;   // 2048, nbs = 4

    moe_gemm_f16<true, __half><<<grid, 128, SMEM_BYTES>>>(
        Xh, W1h, b1, H, EXP_D, EXP_F, njobs1, 6);

    moe_gemm_f16<false, float><<<grid, 128, SMEM_BYTES>>>(
        H, W2h, b2, out, EXP_F, EXP_D, njobs2, 4);
}

// round 17
// speedup vs baseline: 1.0938x; 1.0938x over previous
#include <cuda_runtime.h>
#include <cuda_fp16.h>
#include <cstdint>
#include <math.h>

// ---------------------------------------------------------------------------
// 8-expert FFN, fp32: per expert [2048x2048]@[2048x8192] -> GELU -> @[8192x2048]
// compute_103 portable path. R17 = R15 core (fp16 mma.m16n8k16, BK=64, 3
// stages, 2 CTAs/SM, race-free cross-tile pipeline, HW tanh) reverted from
// the R16 persistent regression, PLUS the w2 transpose-pack fused into
// GEMM1's grid (2048 pack CTAs interleaved 4:1) so the ~130us standalone
// pack pass runs in GEMM1's idle DRAM bandwidth instead of serially.
// ---------------------------------------------------------------------------
#define EXP_E 8
#define EXP_C 2048
#define EXP_D 2048
#define EXP_F 8192

__device__ __align__(256) __half g_H  [(size_t)EXP_E * EXP_C * EXP_F];  // gelu(X@W1+b1)
__device__ __align__(256) __half g_Xh [(size_t)EXP_E * EXP_C * EXP_D];  // half X
__device__ __align__(256) __half g_W1h[(size_t)EXP_E * EXP_D * EXP_F];  // [E][D/64][F][64]
__device__ __align__(256) __half g_W2h[(size_t)EXP_E * EXP_F * EXP_D];  // [E][F/64][D][64]

#define BM 128
#define BN 128
#define BK 64
#define STAGES 3
#define ROW_BYTES 128                       // 64 halves per k-row
#define A_BYTES (BM * ROW_BYTES)            // 16384
#define B_BYTES (BN * ROW_BYTES)            // 16384
#define STAGE_BYTES (A_BYTES + B_BYTES)     // 32768
#define SMEM_BYTES (STAGES * STAGE_BYTES)   // 98304/CTA; 2 CTAs = 192KB/SM

// ---------------------------------------------------------------------------
// Helpers
// ---------------------------------------------------------------------------
__device__ __forceinline__ uint32_t smem_u32(const void* p) {
    uint32_t a;
    asm("{ .reg .u64 t; cvta.to.shared.u64 t, %1; cvt.u32.u64 %0, t; }"
        : "=r"(a) : "l"(p));
    return a;
}

#define CP_ASYNC_CG(dst_u32, src_ptr) \
    asm volatile("cp.async.cg.shared.global [%0], [%1], 16;" \
                 :: "r"(dst_u32), "l"(src_ptr) : "memory")
#define CP_ASYNC_COMMIT() asm volatile("cp.async.commit_group;" ::: "memory")
#define CP_ASYNC_WAIT(n)  asm volatile("cp.async.wait_group %0;" :: "n"(n) : "memory")

#define LDSM_X4(r, addr) \
    asm volatile("ldmatrix.sync.aligned.m8n8.x4.shared.b16 {%0,%1,%2,%3}, [%4];" \
                 : "=r"((r)[0]), "=r"((r)[1]), "=r"((r)[2]), "=r"((r)[3]) \
                 : "r"(addr))

// fp16 MMA, fp32 accumulate
__device__ __forceinline__ void mma_f16(float* d, const uint32_t* a,
                                        uint32_t b0, uint32_t b1) {
    asm volatile(
        "mma.sync.aligned.m16n8k16.row.col.f32.f16.f16.f32 "
        "{%0,%1,%2,%3}, {%4,%5,%6,%7}, {%8,%9}, {%0,%1,%2,%3};"
        : "+f"(d[0]), "+f"(d[1]), "+f"(d[2]), "+f"(d[3])
        : "r"(a[0]), "r"(a[1]), "r"(a[2]), "r"(a[3]), "r"(b0), "r"(b1));
}

// HW tanh (sm_75+ MUFU): single instruction, max err ~2^-11.
__device__ __forceinline__ float tanh_hw(float x) {
    float y;
    asm("tanh.approx.f32 %0, %1;" : "=f"(y) : "f"(x));
    return y;
}

__device__ __forceinline__ float gelu_tanh(float x) {
    float u = 0.7978845608028654f * fmaf(0.044715f * x, x * x, x);
    return 0.5f * x * (1.0f + tanh_hw(u));
}

// Convert X: fp32 -> fp16 (RNE).
__global__ void __launch_bounds__(256)
to_half_pass(const float4* __restrict__ in, uint2* __restrict__ out, size_t n4) {
    size_t i = (size_t)blockIdx.x * blockDim.x + threadIdx.x;
    size_t stride = (size_t)gridDim.x * blockDim.x;
    for (; i < n4; i += stride) {
        float4 v = in[i];
        __half2 h0 = __floats2half2_rn(v.x, v.y);
        __half2 h1 = __floats2half2_rn(v.z, v.w);
        uint2 u;
        u.x = *reinterpret_cast<uint32_t*>(&h0);
        u.y = *reinterpret_cast<uint32_t*>(&h1);
        out[i] = u;
    }
}

// Transpose-pack one 64-k x n-column strip: W[e][k][n] -> Wt[e][k/64][n][64].
__device__ __forceinline__ void pack_strip(const float* __restrict__ src,
                                           __half* __restrict__ dst, int N) {
#pragma unroll
    for (int j = 0; j < 64; j += 8) {
        uint4 u;
        __half2 h;
        h = __floats2half2_rn(src[(size_t)(j+0)*N], src[(size_t)(j+1)*N]);
        u.x = *reinterpret_cast<uint32_t*>(&h);
        h = __floats2half2_rn(src[(size_t)(j+2)*N], src[(size_t)(j+3)*N]);
        u.y = *reinterpret_cast<uint32_t*>(&h);
        h = __floats2half2_rn(src[(size_t)(j+4)*N], src[(size_t)(j+5)*N]);
        u.z = *reinterpret_cast<uint32_t*>(&h);
        h = __floats2half2_rn(src[(size_t)(j+6)*N], src[(size_t)(j+7)*N]);
        u.w = *reinterpret_cast<uint32_t*>(&h);
        *reinterpret_cast<uint4*>(dst + j) = u;
    }
}

// Standalone weight pack (used for w1, which GEMM1 itself needs).
__global__ void __launch_bounds__(256)
transpose_pack64_h(const float* __restrict__ W, __half* __restrict__ Wt,
                   int K, int N) {
    const int n  = blockIdx.x * 256 + threadIdx.x;
    const int kt = blockIdx.y;
    const int e  = blockIdx.z;
    pack_strip(W + ((size_t)e * K + (size_t)kt * 64) * N + n,
               Wt + (((size_t)e * (K / 64) + kt) * N + n) * 64, N);
}

// ---------------------------------------------------------------------------
// Batched GEMM: Out[e][m][n] = epi( sum_k A[e][m][k]*B[e][k][n] + bias[e][n] )
//   A:  [E][2048][K] row-major half;  Bt: [E][K/64][ldN][64] packed half
//   CTA 128x128x64, 128 threads (warp grid 2x2 of 64x64), 2 CTAs/SM.
//   1-D grid; job -> m = job&15 (fastest, shares B in L2), n, e.
//   PACK=true: every 5th CTA instead transpose-packs w2 (EXP_F x EXP_D)
//   into packDst, streaming in GEMM1's idle DRAM bandwidth.
// ---------------------------------------------------------------------------
template <bool GELU, bool PACK, typename OutT>
__global__ void __launch_bounds__(128, 2)
moe_gemm_f16(const __half* __restrict__ A, const __half* __restrict__ Bt,
             const float* __restrict__ bias, OutT* __restrict__ Out,
             int K, int ldN, int nbs,
             const float* __restrict__ packSrc, __half* __restrict__ packDst)
{
    extern __shared__ char smem[];
    const int tid  = threadIdx.x;

    int job;
    if (PACK) {
        const int g = blockIdx.x;
        const int q = g / 5, r = g - q * 5;
        if (r == 4) {
            // ---- pack branch: 8 k-tiles x 128 n of w2 [EXP_F, EXP_D] ----
            const int idx  = q;             // 0..2047
            const int nb   = idx & 15;
            const int rest = idx >> 4;      // 0..127
            const int e2   = rest >> 4;     // 0..7
            const int ktb  = rest & 15;     // 0..15
            const int n    = nb * 128 + tid;
#pragma unroll 1
            for (int jj = 0; jj < 8; ++jj) {
                const int kt = ktb * 8 + jj;
                pack_strip(packSrc + ((size_t)e2 * EXP_F + (size_t)kt * 64) * EXP_D + n,
                           packDst + (((size_t)e2 * (EXP_F / 64) + kt) * EXP_D + n) * 64,
                           EXP_D);
            }
            return;
        }
        job = q * 4 + r;
    } else {
        job = blockIdx.x;
    }

    const int warp = tid >> 5;
    const int lane = tid & 31;
    const int m0 = (job & 15) * BM;
    const int rj = job >> 4;
    const int n0 = (rj & ((1 << nbs) - 1)) * BN;
    const int e  = rj >> nbs;
    const int KT = K / BK;

    const __half* Ae  = A  + (size_t)e * EXP_C * K;
    const __half* Bte = Bt + (size_t)e * (K / 64) * ldN * 64 + (size_t)n0 * 64;
    const float*  be  = bias + (size_t)e * ldN;
    OutT*         Oe  = Out  + (size_t)e * EXP_C * ldN;

    const uint32_t sbase = smem_u32(smem);

    const int wm = warp >> 1;    // warp grid 2(M) x 2(N), warp tile 64x64
    const int wn = warp & 1;

    // ---- cp.async geometry ----
    const int crow   = tid >> 3;              // 0..15
    const int cchunk = tid & 7;               // 8 x 16B per 128B row
    const int cswz   = crow & 7;
    const uint32_t a_dst0 = (uint32_t)(crow * ROW_BYTES + ((cchunk ^ cswz) * 16));

    const __half* a_run = Ae  + (size_t)(m0 + crow) * K + cchunk * 8;
    const __half* b_run = Bte + (size_t)crow * 64 + cchunk * 8;

    // ---- ldmatrix geometry (kk-step address = base ^ (kk*32)) ----
    const int alrow = (lane & 7) + ((lane >> 3) & 1) * 8;
    const int ahi   = lane >> 4;
    const int blrow = (lane & 7) + ((lane >> 4) & 1) * 8;
    const int bhi   = (lane >> 3) & 1;
    uint32_t afrag[4], bfrag[4];
#pragma unroll
    for (int i = 0; i < 4; ++i) {
        int ra = wm * 64 + i * 16 + alrow;
        afrag[i] = (uint32_t)(ra * ROW_BYTES + ((ahi ^ (ra & 7)) * 16));
        int rb = wn * 64 + i * 16 + blrow;
        bfrag[i] = (uint32_t)(A_BYTES + rb * ROW_BYTES + ((bhi ^ (rb & 7)) * 16));
    }

    float acc[4][8][4];
#pragma unroll
    for (int mt = 0; mt < 4; ++mt)
#pragma unroll
        for (int nt = 0; nt < 8; ++nt)
#pragma unroll
            for (int j = 0; j < 4; ++j) acc[mt][nt][j] = 0.0f;

    auto issue_tile = [&](int stg) {
        const uint32_t st = sbase + (uint32_t)stg * STAGE_BYTES;
#pragma unroll
        for (int rep = 0; rep < 8; ++rep)
            CP_ASYNC_CG(st + a_dst0 + rep * 16u * ROW_BYTES,
                        a_run + (size_t)rep * 16 * K);
#pragma unroll
        for (int rep = 0; rep < 8; ++rep)
            CP_ASYNC_CG(st + A_BYTES + a_dst0 + rep * 16u * ROW_BYTES,
                        b_run + rep * 16 * 64);
        a_run += BK;
        b_run += (size_t)ldN * 64;
    };

    // prologue: fill ALL 3 stages (KT >= 3 always here)
#pragma unroll
    for (int t = 0; t < STAGES; ++t) {
        issue_tile(t);
        CP_ASYNC_COMMIT();
    }
    CP_ASYNC_WAIT(2);          // pending {0,1,2} -> tile 0 resident
    __syncthreads();

    // preload tile 0 / kk 0 fragments
    uint32_t af[2][4][4], bf[2][4][4];
#pragma unroll
    for (int i = 0; i < 4; ++i) LDSM_X4(af[0][i], sbase + afrag[i]);
#pragma unroll
    for (int i = 0; i < 4; ++i) LDSM_X4(bf[0][i], sbase + bfrag[i]);

    int s_cur = 0;
    for (int t = 0; t < KT; ++t) {
        const uint32_t sA = sbase + (uint32_t)s_cur * STAGE_BYTES;
        const int s_nxt = (s_cur + 1 == STAGES) ? 0 : s_cur + 1;
        const uint32_t sN = sbase + (uint32_t)s_nxt * STAGE_BYTES;

#pragma unroll
        for (int kk = 0; kk < 4; ++kk) {
            const int cur = kk & 1, nxt = cur ^ 1;
            if (kk < 3) {
                // prefetch fragments for kk+1 (same stage)
                const uint32_t x = (uint32_t)(kk + 1) * 32u;
#pragma unroll
                for (int i = 0; i < 4; ++i) LDSM_X4(af[nxt][i], sA + (afrag[i] ^ x));
#pragma unroll
                for (int i = 0; i < 4; ++i) LDSM_X4(bf[nxt][i], sA + (bfrag[i] ^ x));
            } else {
                // cross-tile boundary BEFORE kk3's MMA burst.
                // Pending groups here are exactly {t+1, t+2}; WAIT(1) is the
                // weakest wait that guarantees tile t+1's data has landed.
                CP_ASYNC_WAIT(1);
                __syncthreads();
                if (t + 1 < KT) {
#pragma unroll
                    for (int i = 0; i < 4; ++i) LDSM_X4(af[nxt][i], sN + afrag[i]);
#pragma unroll
                    for (int i = 0; i < 4; ++i) LDSM_X4(bf[nxt][i], sN + bfrag[i]);
                }
                if (t + STAGES < KT) issue_tile(s_cur);   // tile t+3 -> freed stage
                CP_ASYNC_COMMIT();                        // uniform group count
            }
#pragma unroll
            for (int mt = 0; mt < 4; ++mt)
#pragma unroll
                for (int nt = 0; nt < 8; ++nt)
                    mma_f16(acc[mt][nt], af[cur][mt],
                            bf[cur][nt >> 1][(nt & 1) * 2],
                            bf[cur][nt >> 1][(nt & 1) * 2 + 1]);
        }
        s_cur = s_nxt;
    }

    // ---- epilogue: direct reg -> gmem, fused bias (+GELU via HW tanh) ----
    const int g     = lane >> 2;
    const int cpair = (lane & 3) * 2;
    float2 bv[8];
#pragma unroll
    for (int nt = 0; nt < 8; ++nt)
        bv[nt] = *reinterpret_cast<const float2*>(be + n0 + wn * 64 + nt * 8 + cpair);

#pragma unroll
    for (int mt = 0; mt < 4; ++mt) {
#pragma unroll
        for (int h = 0; h < 2; ++h) {
            const int grow = m0 + wm * 64 + mt * 16 + g + h * 8;
            OutT* op = Oe + (size_t)grow * ldN + n0 + wn * 64 + cpair;
#pragma unroll
            for (int nt = 0; nt < 8; ++nt) {
                float x0 = acc[mt][nt][h * 2]     + bv[nt].x;
                float x1 = acc[mt][nt][h * 2 + 1] + bv[nt].y;
                if (GELU) {
                    __half2 hv = __floats2half2_rn(gelu_tanh(x0), gelu_tanh(x1));
                    *reinterpret_cast<__half2*>((__half*)op + nt * 8) = hv;
                } else {
                    *reinterpret_cast<float2*>((float*)op + nt * 8) =
                        make_float2(x0, x1);
                }
            }
        }
    }
}

// ---------------------------------------------------------------------------
// kernel_launch
// ---------------------------------------------------------------------------
extern "C" void kernel_launch(void* const* d_in, const int* in_sizes, int n_in,
                              void* d_out, int out_size) {
    (void)in_sizes; (void)n_in; (void)out_size;
    const float* inputs = (const float*)d_in[0];
    const float* w1     = (const float*)d_in[1];
    const float* b1     = (const float*)d_in[2];
    const float* w2     = (const float*)d_in[3];
    const float* b2     = (const float*)d_in[4];
    float* out = (float*)d_out;

    void *hp, *xp, *w1p, *w2p;
    cudaGetSymbolAddress(&hp,  g_H);
    cudaGetSymbolAddress(&xp,  g_Xh);
    cudaGetSymbolAddress(&w1p, g_W1h);
    cudaGetSymbolAddress(&w2p, g_W2h);
    __half* H   = (__half*)hp;
    __half* Xh  = (__half*)xp;
    __half* W1h = (__half*)w1p;
    __half* W2h = (__half*)w2p;

    const size_t nX = (size_t)EXP_E * EXP_C * EXP_D / 4;
    to_half_pass<<<2048, 256>>>((const float4*)inputs, (uint2*)Xh, nX);

    // w1 pack must precede GEMM1 (GEMM1 reads it)
    dim3 t1(EXP_F / 256, EXP_D / 64, EXP_E);   // W1: K=D, N=F
    transpose_pack64_h<<<t1, 256>>>(w1, W1h, EXP_D, EXP_F);

    cudaFuncSetAttribute((const void*)moe_gemm_f16<true, true, __half>,
                         cudaFuncAttributeMaxDynamicSharedMemorySize, SMEM_BYTES);
    cudaFuncSetAttribute((const void*)moe_gemm_f16<false, false, float>,
                         cudaFuncAttributeMaxDynamicSharedMemorySize, SMEM_BYTES);

    // GEMM1: 8192 gemm jobs + 2048 w2-pack CTAs, interleaved 4:1 (period 5)
    const int grid1 = 8192 + 2048;             // 10240
    moe_gemm_f16<true, true, __half><<<grid1, 128, SMEM_BYTES>>>(
        Xh, W1h, b1, H, EXP_D, EXP_F, 6, w2, W2h);

    // GEMM2: w2 already packed by GEMM1's fused pack CTAs
    const int grid2 = 2048;
    moe_gemm_f16<false, false, float><<<grid2, 128, SMEM_BYTES>>>(
        H, W2h, b2, out, EXP_F, EXP_D, 4, nullptr, nullptr);
}